// round 3
// baseline (speedup 1.0000x reference)
#include <cuda_runtime.h>
#include <cuda_bf16.h>
#include <math.h>

// Problem constants
#define NN   20000          // nodes
#define NE   320000         // edges
#define CC   128            // channels (CIN == H == 128)
#define KK   27             // kernel matrices
#define NB   (KK * CC)      // 3456 = XW columns
#define EDGE_DIM 16
#define MLP_HID  6

// ---------------- static device scratch (no allocations allowed) ----------------
__device__ int   g_idx64;                 // 1 if edge_index is int64
__device__ int   g_src[NE];
__device__ int   g_dst[NE];
__device__ int   g_kbase[NE];
__device__ float g_bw[NE * 8];
__device__ float g_Bmat[3][CC * NB];      // per-layer W reshaped to [Cin, K*H] row-major
__device__ float g_XW[(size_t)NN * NB];   // 276.5 MB
__device__ float g_h[2][NN * CC];         // ping-pong activations

// tap offsets: bit0*1 + bit1*3 + bit2*9
__device__ __constant__ int c_off[8] = {0, 1, 3, 4, 9, 10, 12, 13};

// ---------------- index width detection ----------------
__global__ void detect_idx_kernel(const unsigned int* __restrict__ ei) {
    if (blockIdx.x == 0 && threadIdx.x == 0) {
        int is64 = 1;
        // stay within first 2*NE 32-bit words (valid for both widths)
        for (int i = 0; i < 4096; i++) {
            if (ei[2 * i + 1] != 0u) { is64 = 0; break; }
        }
        g_idx64 = is64;
    }
}

// ---------------- edge preprocessing: MLP + sigmoid + spline basis ----------------
__global__ void edge_pre_kernel(const void* __restrict__ ei_raw,
                                const float* __restrict__ ea,
                                const float* __restrict__ Wp1,
                                const float* __restrict__ bp1,
                                const float* __restrict__ Wp2,
                                const float* __restrict__ bp2) {
    int e = blockIdx.x * blockDim.x + threadIdx.x;
    if (e >= NE) return;

    int s, d;
    if (g_idx64) {
        const long long* p = (const long long*)ei_raw;
        s = (int)p[e];
        d = (int)p[NE + e];
    } else {
        const int* p = (const int*)ei_raw;
        s = p[e];
        d = p[NE + e];
    }
    g_src[e] = s;
    g_dst[e] = d;

    float a[EDGE_DIM];
#pragma unroll
    for (int i = 0; i < EDGE_DIM; i++) a[i] = ea[(size_t)e * EDGE_DIM + i];

    float h[MLP_HID];
#pragma unroll
    for (int j = 0; j < MLP_HID; j++) {
        float z = bp1[j];
#pragma unroll
        for (int i = 0; i < EDGE_DIM; i++) z += a[i] * Wp1[i * MLP_HID + j];
        h[j] = fmaxf(z, 0.0f);
    }

    float fr[3];
    int lo[3];
#pragma unroll
    for (int dd = 0; dd < 3; dd++) {
        float z = bp2[dd];
#pragma unroll
        for (int j = 0; j < MLP_HID; j++) z += h[j] * Wp2[j * 3 + dd];
        float u = 1.0f / (1.0f + expf(-z));
        float v = u * 2.0f;                       // u * (KS-1)
        float l = fminf(fmaxf(floorf(v), 0.0f), 1.0f);
        lo[dd] = (int)l;
        fr[dd] = v - l;
    }
    g_kbase[e] = lo[0] + 3 * lo[1] + 9 * lo[2];

#pragma unroll
    for (int sb = 0; sb < 8; sb++) {
        float w = ((sb & 1) ? fr[0] : 1.0f - fr[0])
                * ((sb & 2) ? fr[1] : 1.0f - fr[1])
                * ((sb & 4) ? fr[2] : 1.0f - fr[2]);
        g_bw[(size_t)e * 8 + sb] = w;
    }
}

// ---------------- reshape W [K,Cin,H] -> Bmat [Cin, K*H] ----------------
__global__ void transpose_w_kernel(const float* __restrict__ W, float* __restrict__ Bmat) {
    int idx = blockIdx.x * blockDim.x + threadIdx.x;
    if (idx >= KK * CC * CC) return;
    int o = idx & 127;
    int rem = idx >> 7;
    int i = rem & 127;
    int k = rem >> 7;
    Bmat[(size_t)i * NB + k * CC + o] = W[idx];
}

// ---------------- fp32 SGEMM, K=128 fixed, C = A@B (+bias) ----------------
__global__ void __launch_bounds__(256)
sgemm128_kernel(const float* __restrict__ A, const float* __restrict__ B,
                const float* __restrict__ bias, float* __restrict__ C,
                int M, int N, int hasBias) {
    __shared__ float As[32][132];
    __shared__ float Bs[32][128];
    int tid = threadIdx.x;
    int bm = blockIdx.y * 128;
    int bn = blockIdx.x * 128;
    int tx = tid & 15, ty = tid >> 4;

    float acc[8][8];
#pragma unroll
    for (int i = 0; i < 8; i++)
#pragma unroll
        for (int j = 0; j < 8; j++) acc[i][j] = 0.0f;

    int arow  = tid >> 3;          // 0..31
    int acol4 = (tid & 7) * 4;     // 0..28
    int brow  = tid >> 5;          // 0..7
    int bcol4 = (tid & 31) * 4;    // 0..124

    for (int kk = 0; kk < 128; kk += 32) {
#pragma unroll
        for (int p = 0; p < 4; p++) {
            int r  = arow + 32 * p;
            int gr = bm + r;
            float4 v = make_float4(0.f, 0.f, 0.f, 0.f);
            if (gr < M) v = *(const float4*)(A + (size_t)gr * 128 + kk + acol4);
            As[acol4 + 0][r] = v.x;
            As[acol4 + 1][r] = v.y;
            As[acol4 + 2][r] = v.z;
            As[acol4 + 3][r] = v.w;
        }
#pragma unroll
        for (int p = 0; p < 4; p++) {
            int kr = brow + 8 * p;
            float4 v = *(const float4*)(B + (size_t)(kk + kr) * N + bn + bcol4);
            *(float4*)&Bs[kr][bcol4] = v;
        }
        __syncthreads();
#pragma unroll
        for (int k = 0; k < 32; k++) {
            float a[8], b[8];
#pragma unroll
            for (int i = 0; i < 8; i++) a[i] = As[k][ty * 8 + i];
#pragma unroll
            for (int j = 0; j < 8; j++) b[j] = Bs[k][tx * 8 + j];
#pragma unroll
            for (int i = 0; i < 8; i++)
#pragma unroll
                for (int j = 0; j < 8; j++) acc[i][j] += a[i] * b[j];
        }
        __syncthreads();
    }

#pragma unroll
    for (int i = 0; i < 8; i++) {
        int gr = bm + ty * 8 + i;
        if (gr >= M) continue;
#pragma unroll
        for (int j = 0; j < 8; j += 4) {
            int gc = bn + tx * 8 + j;
            float4 v = make_float4(acc[i][j], acc[i][j + 1], acc[i][j + 2], acc[i][j + 3]);
            if (hasBias) {
                v.x += bias[gc];
                v.y += bias[gc + 1];
                v.z += bias[gc + 2];
                v.w += bias[gc + 3];
            }
            *(float4*)(C + (size_t)gr * N + gc) = v;
        }
    }
}

// ---------------- edge aggregation: out[dst] += sum_s bw_s * XW[src, k_s, :] ----------------
__global__ void __launch_bounds__(256)
agg_kernel(const float* __restrict__ XW, float* __restrict__ out) {
    int warp = (blockIdx.x * blockDim.x + threadIdx.x) >> 5;
    int lane = threadIdx.x & 31;
    if (warp >= NE) return;
    int e  = warp;
    int s  = g_src[e];
    int d  = g_dst[e];
    int kb = g_kbase[e];

    float wv = 0.0f;
    if (lane < 8) wv = g_bw[(size_t)e * 8 + lane];

    const float* row = XW + (size_t)s * NB + (size_t)kb * CC;
    float4 acc = make_float4(0.f, 0.f, 0.f, 0.f);
#pragma unroll
    for (int t = 0; t < 8; t++) {
        float w = __shfl_sync(0xffffffffu, wv, t);
        float4 v = *(const float4*)(row + c_off[t] * CC + lane * 4);
        acc.x += w * v.x;
        acc.y += w * v.y;
        acc.z += w * v.z;
        acc.w += w * v.w;
    }
    float* op = out + (size_t)d * CC + lane * 4;
    atomicAdd(op + 0, acc.x);
    atomicAdd(op + 1, acc.y);
    atomicAdd(op + 2, acc.z);
    atomicAdd(op + 3, acc.w);
}

// ---------------- in-place ReLU ----------------
__global__ void relu_kernel(float* __restrict__ h) {
    int i = blockIdx.x * blockDim.x + threadIdx.x;
    if (i >= NN * CC / 4) return;
    float4 v = *((float4*)h + i);
    v.x = fmaxf(v.x, 0.f);
    v.y = fmaxf(v.y, 0.f);
    v.z = fmaxf(v.z, 0.f);
    v.w = fmaxf(v.w, 0.f);
    *((float4*)h + i) = v;
}

// ---------------- launch ----------------
extern "C" void kernel_launch(void* const* d_in, const int* in_sizes, int n_in,
                              void* d_out, int out_size) {
    const float* x    = (const float*)d_in[0];
    const void*  ei   = d_in[1];
    const float* ea   = (const float*)d_in[2];
    const float* Wp1  = (const float*)d_in[3];
    const float* bp1  = (const float*)d_in[4];
    const float* Wp2  = (const float*)d_in[5];
    const float* bp2  = (const float*)d_in[6];
    const float* W[3]  = {(const float*)d_in[7],  (const float*)d_in[10], (const float*)d_in[13]};
    const float* Wr[3] = {(const float*)d_in[8],  (const float*)d_in[11], (const float*)d_in[14]};
    const float* b[3]  = {(const float*)d_in[9],  (const float*)d_in[12], (const float*)d_in[15]};
    float* out_final = (float*)d_out;

    float* g_XW_p;    cudaGetSymbolAddress((void**)&g_XW_p, g_XW);
    float* g_h_p;     cudaGetSymbolAddress((void**)&g_h_p, g_h);
    float* g_Bmat_p;  cudaGetSymbolAddress((void**)&g_Bmat_p, g_Bmat);

    // 1) detect edge_index width
    detect_idx_kernel<<<1, 32>>>((const unsigned int*)ei);

    // 2) edge preprocessing (shared by all layers)
    edge_pre_kernel<<<(NE + 255) / 256, 256>>>(ei, ea, Wp1, bp1, Wp2, bp2);

    // 3) reshape weights once
    for (int l = 0; l < 3; l++) {
        transpose_w_kernel<<<(KK * CC * CC + 255) / 256, 256>>>(
            W[l], g_Bmat_p + (size_t)l * CC * NB);
    }

    // 4) three layers
    const float* act = x;
    dim3 gridXW(NB / 128, (NN + 127) / 128);
    dim3 gridRoot(1, (NN + 127) / 128);
    int aggBlocks  = (NE * 32 + 255) / 256;
    int reluBlocks = (NN * CC / 4 + 255) / 256;

    for (int l = 0; l < 3; l++) {
        float* outbuf = (l == 2) ? out_final : (g_h_p + (size_t)l * NN * CC);

        // XW = act @ Bmat_l   [NN,128] @ [128, 3456]
        sgemm128_kernel<<<gridXW, 256>>>(act, g_Bmat_p + (size_t)l * CC * NB,
                                         nullptr, g_XW_p, NN, NB, 0);
        // out = act @ Wr_l + b_l   (initializes outbuf)
        sgemm128_kernel<<<gridRoot, 256>>>(act, Wr[l], b[l], outbuf, NN, CC, 1);

        // out[dst] += sum_s bw * XW[src, k_s]
        agg_kernel<<<aggBlocks, 256>>>(g_XW_p, outbuf);

        if (l < 2) {
            relu_kernel<<<reluBlocks, 256>>>(outbuf);
            act = outbuf;
        }
    }
}

// round 4
// speedup vs baseline: 1.0014x; 1.0014x over previous
#include <cuda_runtime.h>
#include <cuda_bf16.h>
#include <math.h>

// Problem constants
#define NN   20000          // nodes
#define NE   320000         // edges
#define CC   128            // channels (CIN == H == 128)
#define KK   27             // kernel matrices
#define NB   (KK * CC)      // 3456 = XW columns
#define EDGE_DIM 16
#define MLP_HID  6

// ---------------- static device scratch (no allocations allowed) ----------------
__device__ int   g_idx64;                 // 1 if edge_index is int64
__device__ int   g_src[NE];
__device__ int   g_dst[NE];
__device__ int   g_kbase[NE];
__device__ float g_bw[NE * 8];
__device__ float g_Bmat[3][CC * NB];      // per-layer W reshaped to [Cin, K*H] row-major
__device__ float g_XW[(size_t)NN * NB];   // 276.5 MB
__device__ float g_h[2][NN * CC];         // ping-pong activations

// tap offsets: bit0*1 + bit1*3 + bit2*9
__device__ __constant__ int c_off[8] = {0, 1, 3, 4, 9, 10, 12, 13};

// ---------------- index width detection ----------------
__global__ void detect_idx_kernel(const unsigned int* __restrict__ ei) {
    if (blockIdx.x == 0 && threadIdx.x == 0) {
        int is64 = 1;
        // stay within first 2*NE 32-bit words (valid for both widths)
        for (int i = 0; i < 4096; i++) {
            if (ei[2 * i + 1] != 0u) { is64 = 0; break; }
        }
        g_idx64 = is64;
    }
}

// ---------------- edge preprocessing: MLP + sigmoid + spline basis ----------------
__global__ void edge_pre_kernel(const void* __restrict__ ei_raw,
                                const float* __restrict__ ea,
                                const float* __restrict__ Wp1,
                                const float* __restrict__ bp1,
                                const float* __restrict__ Wp2,
                                const float* __restrict__ bp2) {
    int e = blockIdx.x * blockDim.x + threadIdx.x;
    if (e >= NE) return;

    int s, d;
    if (g_idx64) {
        const long long* p = (const long long*)ei_raw;
        s = (int)p[e];
        d = (int)p[NE + e];
    } else {
        const int* p = (const int*)ei_raw;
        s = p[e];
        d = p[NE + e];
    }
    g_src[e] = s;
    g_dst[e] = d;

    float a[EDGE_DIM];
#pragma unroll
    for (int i = 0; i < EDGE_DIM; i++) a[i] = ea[(size_t)e * EDGE_DIM + i];

    float h[MLP_HID];
#pragma unroll
    for (int j = 0; j < MLP_HID; j++) {
        float z = bp1[j];
#pragma unroll
        for (int i = 0; i < EDGE_DIM; i++) z += a[i] * Wp1[i * MLP_HID + j];
        h[j] = fmaxf(z, 0.0f);
    }

    float fr[3];
    int lo[3];
#pragma unroll
    for (int dd = 0; dd < 3; dd++) {
        float z = bp2[dd];
#pragma unroll
        for (int j = 0; j < MLP_HID; j++) z += h[j] * Wp2[j * 3 + dd];
        float u = 1.0f / (1.0f + expf(-z));
        float v = u * 2.0f;                       // u * (KS-1)
        float l = fminf(fmaxf(floorf(v), 0.0f), 1.0f);
        lo[dd] = (int)l;
        fr[dd] = v - l;
    }
    g_kbase[e] = lo[0] + 3 * lo[1] + 9 * lo[2];

#pragma unroll
    for (int sb = 0; sb < 8; sb++) {
        float w = ((sb & 1) ? fr[0] : 1.0f - fr[0])
                * ((sb & 2) ? fr[1] : 1.0f - fr[1])
                * ((sb & 4) ? fr[2] : 1.0f - fr[2]);
        g_bw[(size_t)e * 8 + sb] = w;
    }
}

// ---------------- reshape W [K,Cin,H] -> Bmat [Cin, K*H] ----------------
__global__ void transpose_w_kernel(const float* __restrict__ W, float* __restrict__ Bmat) {
    int idx = blockIdx.x * blockDim.x + threadIdx.x;
    if (idx >= KK * CC * CC) return;
    int o = idx & 127;
    int rem = idx >> 7;
    int i = rem & 127;
    int k = rem >> 7;
    Bmat[(size_t)i * NB + k * CC + o] = W[idx];
}

// ---------------- fp32 SGEMM, K=128 fixed, C = A@B (+bias) ----------------
__global__ void __launch_bounds__(256)
sgemm128_kernel(const float* __restrict__ A, const float* __restrict__ B,
                const float* __restrict__ bias, float* __restrict__ C,
                int M, int N, int hasBias) {
    __shared__ float As[32][132];
    __shared__ float Bs[32][128];
    int tid = threadIdx.x;
    int bm = blockIdx.y * 128;
    int bn = blockIdx.x * 128;
    int tx = tid & 15, ty = tid >> 4;

    float acc[8][8];
#pragma unroll
    for (int i = 0; i < 8; i++)
#pragma unroll
        for (int j = 0; j < 8; j++) acc[i][j] = 0.0f;

    int arow  = tid >> 3;          // 0..31
    int acol4 = (tid & 7) * 4;     // 0..28
    int brow  = tid >> 5;          // 0..7
    int bcol4 = (tid & 31) * 4;    // 0..124

    for (int kk = 0; kk < 128; kk += 32) {
#pragma unroll
        for (int p = 0; p < 4; p++) {
            int r  = arow + 32 * p;
            int gr = bm + r;
            float4 v = make_float4(0.f, 0.f, 0.f, 0.f);
            if (gr < M) v = *(const float4*)(A + (size_t)gr * 128 + kk + acol4);
            As[acol4 + 0][r] = v.x;
            As[acol4 + 1][r] = v.y;
            As[acol4 + 2][r] = v.z;
            As[acol4 + 3][r] = v.w;
        }
#pragma unroll
        for (int p = 0; p < 4; p++) {
            int kr = brow + 8 * p;
            float4 v = *(const float4*)(B + (size_t)(kk + kr) * N + bn + bcol4);
            *(float4*)&Bs[kr][bcol4] = v;
        }
        __syncthreads();
#pragma unroll
        for (int k = 0; k < 32; k++) {
            float a[8], b[8];
#pragma unroll
            for (int i = 0; i < 8; i++) a[i] = As[k][ty * 8 + i];
#pragma unroll
            for (int j = 0; j < 8; j++) b[j] = Bs[k][tx * 8 + j];
#pragma unroll
            for (int i = 0; i < 8; i++)
#pragma unroll
                for (int j = 0; j < 8; j++) acc[i][j] += a[i] * b[j];
        }
        __syncthreads();
    }

#pragma unroll
    for (int i = 0; i < 8; i++) {
        int gr = bm + ty * 8 + i;
        if (gr >= M) continue;
#pragma unroll
        for (int j = 0; j < 8; j += 4) {
            int gc = bn + tx * 8 + j;
            float4 v = make_float4(acc[i][j], acc[i][j + 1], acc[i][j + 2], acc[i][j + 3]);
            if (hasBias) {
                v.x += bias[gc];
                v.y += bias[gc + 1];
                v.z += bias[gc + 2];
                v.w += bias[gc + 3];
            }
            *(float4*)(C + (size_t)gr * N + gc) = v;
        }
    }
}

// ---------------- edge aggregation: out[dst] += sum_s bw_s * XW[src, k_s, :] ----------------
__global__ void __launch_bounds__(256)
agg_kernel(const float* __restrict__ XW, float* __restrict__ out) {
    int warp = (blockIdx.x * blockDim.x + threadIdx.x) >> 5;
    int lane = threadIdx.x & 31;
    if (warp >= NE) return;
    int e  = warp;
    int s  = g_src[e];
    int d  = g_dst[e];
    int kb = g_kbase[e];

    float wv = 0.0f;
    if (lane < 8) wv = g_bw[(size_t)e * 8 + lane];

    const float* row = XW + (size_t)s * NB + (size_t)kb * CC;
    float4 acc = make_float4(0.f, 0.f, 0.f, 0.f);
#pragma unroll
    for (int t = 0; t < 8; t++) {
        float w = __shfl_sync(0xffffffffu, wv, t);
        float4 v = *(const float4*)(row + c_off[t] * CC + lane * 4);
        acc.x += w * v.x;
        acc.y += w * v.y;
        acc.z += w * v.z;
        acc.w += w * v.w;
    }
    float* op = out + (size_t)d * CC + lane * 4;
    atomicAdd(op + 0, acc.x);
    atomicAdd(op + 1, acc.y);
    atomicAdd(op + 2, acc.z);
    atomicAdd(op + 3, acc.w);
}

// ---------------- in-place ReLU ----------------
__global__ void relu_kernel(float* __restrict__ h) {
    int i = blockIdx.x * blockDim.x + threadIdx.x;
    if (i >= NN * CC / 4) return;
    float4 v = *((float4*)h + i);
    v.x = fmaxf(v.x, 0.f);
    v.y = fmaxf(v.y, 0.f);
    v.z = fmaxf(v.z, 0.f);
    v.w = fmaxf(v.w, 0.f);
    *((float4*)h + i) = v;
}

// ---------------- launch ----------------
extern "C" void kernel_launch(void* const* d_in, const int* in_sizes, int n_in,
                              void* d_out, int out_size) {
    const float* x    = (const float*)d_in[0];
    const void*  ei   = d_in[1];
    const float* ea   = (const float*)d_in[2];
    const float* Wp1  = (const float*)d_in[3];
    const float* bp1  = (const float*)d_in[4];
    const float* Wp2  = (const float*)d_in[5];
    const float* bp2  = (const float*)d_in[6];
    const float* W[3]  = {(const float*)d_in[7],  (const float*)d_in[10], (const float*)d_in[13]};
    const float* Wr[3] = {(const float*)d_in[8],  (const float*)d_in[11], (const float*)d_in[14]};
    const float* b[3]  = {(const float*)d_in[9],  (const float*)d_in[12], (const float*)d_in[15]};
    float* out_final = (float*)d_out;

    float* g_XW_p;    cudaGetSymbolAddress((void**)&g_XW_p, g_XW);
    float* g_h_p;     cudaGetSymbolAddress((void**)&g_h_p, g_h);
    float* g_Bmat_p;  cudaGetSymbolAddress((void**)&g_Bmat_p, g_Bmat);

    // 1) detect edge_index width
    detect_idx_kernel<<<1, 32>>>((const unsigned int*)ei);

    // 2) edge preprocessing (shared by all layers)
    edge_pre_kernel<<<(NE + 255) / 256, 256>>>(ei, ea, Wp1, bp1, Wp2, bp2);

    // 3) reshape weights once
    for (int l = 0; l < 3; l++) {
        transpose_w_kernel<<<(KK * CC * CC + 255) / 256, 256>>>(
            W[l], g_Bmat_p + (size_t)l * CC * NB);
    }

    // 4) three layers
    const float* act = x;
    dim3 gridXW(NB / 128, (NN + 127) / 128);
    dim3 gridRoot(1, (NN + 127) / 128);
    int aggBlocks  = (NE * 32 + 255) / 256;
    int reluBlocks = (NN * CC / 4 + 255) / 256;

    for (int l = 0; l < 3; l++) {
        float* outbuf = (l == 2) ? out_final : (g_h_p + (size_t)l * NN * CC);

        // XW = act @ Bmat_l   [NN,128] @ [128, 3456]
        sgemm128_kernel<<<gridXW, 256>>>(act, g_Bmat_p + (size_t)l * CC * NB,
                                         nullptr, g_XW_p, NN, NB, 0);
        // out = act @ Wr_l + b_l   (initializes outbuf)
        sgemm128_kernel<<<gridRoot, 256>>>(act, Wr[l], b[l], outbuf, NN, CC, 1);

        // out[dst] += sum_s bw * XW[src, k_s]
        agg_kernel<<<aggBlocks, 256>>>(g_XW_p, outbuf);

        if (l < 2) {
            relu_kernel<<<reluBlocks, 256>>>(outbuf);
            act = outbuf;
        }
    }
}